// round 11
// baseline (speedup 1.0000x reference)
#include <cuda_runtime.h>
#include <cuda_fp16.h>
#include <math.h>
#include <stdint.h>

#define DIM   2048
#define INTER 1408
#define NE    15
#define TMAX  4096
#define KC    32
// stage layout (bytes): AH[0,8K) BH[8K,16K)
#define STAGE 16384
#define NST   6

// ---------------- device scratch ----------------
__device__ int   g_count[NE];
__device__ int   g_offset[NE + 1];
__device__ int   g_tok[NE * TMAX];
__device__ float g_wt[NE * TMAX];
__device__ int   g_exp[2 * TMAX];
__device__ int   g_pos[2 * TMAX];
__device__ __half g_xh[(size_t)TMAX * DIM];
__device__ __half g_w1h[(size_t)NE * INTER * DIM];
__device__ __half g_w3h[(size_t)NE * INTER * DIM];
__device__ __half g_w2h[(size_t)NE * DIM * INTER];
__device__ __half g_sw1h[(size_t)INTER * DIM];
__device__ __half g_sw3h[(size_t)INTER * DIM];
__device__ __half g_sw2h[(size_t)DIM * INTER];
__device__ __half g_hh[(size_t)3 * TMAX * INTER];
__device__ float  g_d[(size_t)3 * TMAX * DIM];   // down results, compacted rows

// ---------------- helpers ----------------
__device__ __forceinline__ uint32_t smem_u32(const void* p) {
    uint32_t a;
    asm("{ .reg .u64 t; cvta.to.shared.u64 t, %1; cvt.u32.u64 %0, t; }" : "=r"(a) : "l"(p));
    return a;
}
// swizzled byte offset inside a 128x32 fp16 tile (64B rows, 4 chunks of 16B)
__device__ __forceinline__ uint32_t toff(uint32_t r, uint32_t c) {
    return r * 64u + ((c ^ ((r >> 1) & 3u)) << 4);
}
__device__ __forceinline__ void ldsm4(uint32_t r[4], uint32_t a) {
    asm volatile("ldmatrix.sync.aligned.m8n8.x4.shared.b16 {%0,%1,%2,%3},[%4];"
                 : "=r"(r[0]), "=r"(r[1]), "=r"(r[2]), "=r"(r[3]) : "r"(a));
}
__device__ __forceinline__ void mma_f16(float c[4], const uint32_t a[4], const uint32_t b[2]) {
    asm volatile("mma.sync.aligned.m16n8k16.row.col.f32.f16.f16.f32 "
                 "{%0,%1,%2,%3},{%4,%5,%6,%7},{%8,%9},{%0,%1,%2,%3};"
                 : "+f"(c[0]), "+f"(c[1]), "+f"(c[2]), "+f"(c[3])
                 : "r"(a[0]), "r"(a[1]), "r"(a[2]), "r"(a[3]), "r"(b[0]), "r"(b[1]));
}
__device__ __forceinline__ void cpa16(uint32_t s, const void* g) {
    asm volatile("cp.async.cg.shared.global [%0], [%1], 16;" :: "r"(s), "l"(g));
}
__device__ __forceinline__ void cpcommit() { asm volatile("cp.async.commit_group;"); }
template <int N> __device__ __forceinline__ void cpwait() {
    asm volatile("cp.async.wait_group %0;" :: "n"(N));
}

// one k-chunk, 64x64 warp tile: c += ah*bh
__device__ __forceinline__ void compute_iter64(float acc[4][8][4], uint32_t base,
                                               int wm, int wn, int arow, int asel,
                                               int brow, int bsel) {
#pragma unroll
    for (int ks = 0; ks < 2; ks++) {
        uint32_t ah[4][4];
#pragma unroll
        for (int mt = 0; mt < 4; mt++) {
            uint32_t ao = toff((uint32_t)(wm + mt * 16 + arow), (uint32_t)(ks * 2 + asel));
            ldsm4(ah[mt], base + ao);
        }
#pragma unroll
        for (int nb = 0; nb < 4; nb++) {
            uint32_t bo = toff((uint32_t)(wn + nb * 16 + brow), (uint32_t)(ks * 2 + bsel));
            uint32_t bh[4];
            ldsm4(bh, base + 8192 + bo);
#pragma unroll
            for (int mt = 0; mt < 4; mt++)
#pragma unroll
                for (int ns = 0; ns < 2; ns++)
                    mma_f16(acc[mt][nb * 2 + ns], ah[mt], bh + ns * 2);
        }
    }
}

// ---------------- converts (4 elems/thread, coalesced) ----------------
__global__ void cvt_hi_kernel(const float4* __restrict__ in, uint2* __restrict__ hi, int n4) {
    int i = blockIdx.x * 1024 + threadIdx.x;
#pragma unroll
    for (int j = 0; j < 4; j++, i += 256) {
        if (i < n4) {
            float4 v = in[i];
            __half2 a = __floats2half2_rn(v.x, v.y), b = __floats2half2_rn(v.z, v.w);
            hi[i] = make_uint2(*(uint32_t*)&a, *(uint32_t*)&b);
        }
    }
}

// ---------------- gating: warp per token ----------------
__global__ void reset_kernel() { if (threadIdx.x < NE) g_count[threadIdx.x] = 0; }

__global__ void gate_kernel(const float* __restrict__ x,
                            const float* __restrict__ gw, int T) {
    int warp = threadIdx.x >> 5, lane = threadIdx.x & 31;
    int t = blockIdx.x * 8 + warp;
    if (t >= T) return;
    const float4* xt = (const float4*)(x + (size_t)t * DIM);
    const float4* gwv = (const float4*)gw;
    float acc[NE];
#pragma unroll
    for (int e = 0; e < NE; e++) acc[e] = 0.f;
    for (int k = lane; k < DIM / 4; k += 32) {
        float4 xv = xt[k];
#pragma unroll
        for (int e = 0; e < NE; e++) {
            float4 wv = gwv[e * (DIM / 4) + k];
            acc[e] += xv.x * wv.x + xv.y * wv.y + xv.z * wv.z + xv.w * wv.w;
        }
    }
#pragma unroll
    for (int e = 0; e < NE; e++)
#pragma unroll
        for (int o = 16; o > 0; o >>= 1)
            acc[e] += __shfl_xor_sync(0xffffffffu, acc[e], o);
    if (lane == 0) {
        float mx = -1e30f;
#pragma unroll
        for (int e = 0; e < NE; e++) mx = fmaxf(mx, acc[e]);
        float p[NE], sum = 0.f;
#pragma unroll
        for (int e = 0; e < NE; e++) { p[e] = expf(acc[e] - mx); sum += p[e]; }
        int i1 = 0;
        for (int e = 1; e < NE; e++) if (acc[e] > acc[i1]) i1 = e;
        int i2 = (i1 == 0) ? 1 : 0;
        for (int e = 0; e < NE; e++) if (e != i1 && acc[e] > acc[i2]) i2 = e;
        float inv = 1.f / sum;
        int idx[2] = {i1, i2};
#pragma unroll
        for (int ssel = 0; ssel < 2; ssel++) {
            int e = idx[ssel];
            int pos = atomicAdd(&g_count[e], 1);
            g_tok[e * TMAX + pos] = t;
            g_wt[e * TMAX + pos]  = p[e] * inv;
            g_exp[2 * t + ssel] = e;
            g_pos[2 * t + ssel] = pos;
        }
    }
}

__global__ void offset_kernel() {
    int s = 0;
    for (int e = 0; e < NE; e++) { g_offset[e] = s; s += g_count[e]; }
    g_offset[NE] = s;
}

// ---------------- fused up GEMM: h = silu(X W1^T)*(X W3^T)*wt -------------
// 128 threads, 4 warps of 64x64. Warp layout: wm=(wid&1)*64, wn=(wid>>1)*64.
// B tile rows [0,64)=W1 cols n0.., [64,128)=W3 same cols -> warps wn=0 hold
// u1, warps wn=64 hold u3 at identical fragment coords.
// grid: (INTER/64=22, 32, nz); e = z0 + blockIdx.z; e==NE => shared expert
__global__ void __launch_bounds__(128, 2) gemm_up(int T, int z0) {
    int e = z0 + blockIdx.z;
    bool se = (e == NE);
    int count = se ? T : g_count[e];
    int row0 = blockIdx.y * 128;
    if (row0 >= count) return;
    int hbase = se ? 2 * T : g_offset[e];
    const __half* W1h = se ? g_sw1h : g_w1h + (size_t)e * INTER * DIM;
    const __half* W3h = se ? g_sw3h : g_w3h + (size_t)e * INTER * DIM;
    int n0 = blockIdx.x * 64;

    extern __shared__ __align__(128) char smem[];
    __shared__ int stok[128];
    __shared__ float swt[128];
    int tid = threadIdx.x, wid = tid >> 5, lane = tid & 31;
    {
        int r = row0 + tid;
        int rc = (r < count) ? r : count - 1;
        stok[tid] = se ? rc : g_tok[e * TMAX + rc];
        swt[tid]  = (se || r >= count) ? 1.f : g_wt[e * TMAX + r];
    }
    __syncthreads();

    uint32_t sb = smem_u32(smem);
    uint32_t soff[4], aoff[4];
    const __half* bptr[4];
#pragma unroll
    for (int j = 0; j < 4; j++) {
        int chunk = tid + j * 128;
        int r = chunk >> 2, c4 = chunk & 3;
        soff[j] = toff((uint32_t)r, (uint32_t)c4);
        aoff[j] = (uint32_t)stok[r] * DIM + c4 * 8;
        bptr[j] = ((r < 64) ? (W1h + (size_t)(n0 + r) * DIM)
                            : (W3h + (size_t)(n0 + r - 64) * DIM)) + c4 * 8;
    }

    const int NIT = DIM / KC;  // 64 (even)
    auto issue = [&](int itn) {
        if (itn < NIT) {
            uint32_t db = sb + (uint32_t)(itn % NST) * STAGE;
            int kk = itn * KC;
#pragma unroll
            for (int j = 0; j < 4; j++) {
                cpa16(db + soff[j],        g_xh + aoff[j] + kk);
                cpa16(db + 8192 + soff[j], bptr[j] + kk);
            }
        }
        cpcommit();
    };
    issue(0); issue(1); issue(2); issue(3);

    int arow = lane & 15, asel = lane >> 4;
    int brow = (lane & 7) + ((lane & 16) >> 1), bsel = (lane >> 3) & 1;
    int wm = (wid & 1) * 64, wn = (wid >> 1) * 64;

    float acc[4][8][4] = {};
    for (int it = 0; it < NIT; it += 2) {
        cpwait<2>();
        __syncthreads();
        issue(it + 4);
        issue(it + 5);
        compute_iter64(acc, sb + (uint32_t)(it % NST) * STAGE,
                       wm, wn, arow, asel, brow, bsel);
        compute_iter64(acc, sb + (uint32_t)((it + 1) % NST) * STAGE,
                       wm, wn, arow, asel, brow, bsel);
    }
    cpwait<0>();
    __syncthreads();

    // epilogue: warps with wn=64 hold u3 at same coords as wn=0 warps' u1
    float* ex = (float*)smem;  // 128 x 66 fp32 exchange (33.8 KB < 96 KB)
    if (wn == 64) {
#pragma unroll
        for (int mt = 0; mt < 4; mt++)
#pragma unroll
            for (int j = 0; j < 8; j++)
#pragma unroll
                for (int h = 0; h < 2; h++) {
                    int lr = wm + mt * 16 + (lane >> 2) + h * 8;
                    int col = j * 8 + (lane & 3) * 2;
                    ex[lr * 66 + col]     = acc[mt][j][h * 2];
                    ex[lr * 66 + col + 1] = acc[mt][j][h * 2 + 1];
                }
    }
    __syncthreads();
    if (wn == 0) {
#pragma unroll
        for (int mt = 0; mt < 4; mt++)
#pragma unroll
            for (int j = 0; j < 8; j++)
#pragma unroll
                for (int h = 0; h < 2; h++) {
                    int lr = wm + mt * 16 + (lane >> 2) + h * 8;
                    if (row0 + lr < count) {
                        int col = j * 8 + (lane & 3) * 2;
                        float wt = swt[lr];
                        float u1a = acc[mt][j][h * 2],     u3a = ex[lr * 66 + col];
                        float u1b = acc[mt][j][h * 2 + 1], u3b = ex[lr * 66 + col + 1];
                        float ha = (u1a / (1.f + expf(-u1a))) * u3a * wt;
                        float hb = (u1b / (1.f + expf(-u1b))) * u3b * wt;
                        __half2 H = __floats2half2_rn(ha, hb);
                        size_t o = (size_t)(hbase + row0 + lr) * INTER + n0 + col;
                        *(__half2*)(g_hh + o) = H;
                    }
                }
    }
}

// ---------------- down GEMM: g_d = H_hi W2h^T -------------------------------
// 128 threads, 4 warps of 64x64.
// grid: (DIM/128=16, 32, nz); z = z0 + blockIdx.z; z==NE => shared expert
__global__ void __launch_bounds__(128, 2) gemm_down(int T, int z0) {
    int z = z0 + blockIdx.z;
    bool se = (z == NE);
    int count = se ? T : g_count[z];
    int row0 = blockIdx.y * 128;
    if (row0 >= count) return;
    int hbase = se ? 2 * T : g_offset[z];
    const __half* Bh = se ? g_sw2h : g_w2h + (size_t)z * DIM * INTER;
    int n0 = blockIdx.x * 128;

    extern __shared__ __align__(128) char smem[];
    int tid = threadIdx.x, wid = tid >> 5, lane = tid & 31;

    uint32_t sb = smem_u32(smem);
    uint32_t soff[4], aoff[4];
    const __half* bptr[4];
#pragma unroll
    for (int j = 0; j < 4; j++) {
        int chunk = tid + j * 128;
        int r = chunk >> 2, c4 = chunk & 3;
        soff[j] = toff((uint32_t)r, (uint32_t)c4);
        int rr = row0 + r;
        int hr = hbase + ((rr < count) ? rr : count - 1);
        aoff[j] = (uint32_t)hr * INTER + c4 * 8;
        bptr[j] = Bh + (size_t)(n0 + r) * INTER + c4 * 8;
    }

    const int NIT = INTER / KC;  // 44 (even)
    auto issue = [&](int itn) {
        if (itn < NIT) {
            uint32_t db = sb + (uint32_t)(itn % NST) * STAGE;
            int kk = itn * KC;
#pragma unroll
            for (int j = 0; j < 4; j++) {
                cpa16(db + soff[j],        g_hh + aoff[j] + kk);
                cpa16(db + 8192 + soff[j], bptr[j] + kk);
            }
        }
        cpcommit();
    };
    issue(0); issue(1); issue(2); issue(3);

    int arow = lane & 15, asel = lane >> 4;
    int brow = (lane & 7) + ((lane & 16) >> 1), bsel = (lane >> 3) & 1;
    int wm = (wid & 1) * 64, wn = (wid >> 1) * 64;

    float acc[4][8][4] = {};
    for (int it = 0; it < NIT; it += 2) {
        cpwait<2>();
        __syncthreads();
        issue(it + 4);
        issue(it + 5);
        compute_iter64(acc, sb + (uint32_t)(it % NST) * STAGE,
                       wm, wn, arow, asel, brow, bsel);
        compute_iter64(acc, sb + (uint32_t)((it + 1) % NST) * STAGE,
                       wm, wn, arow, asel, brow, bsel);
    }

#pragma unroll
    for (int mt = 0; mt < 4; mt++)
#pragma unroll
        for (int j = 0; j < 8; j++)
#pragma unroll
            for (int h = 0; h < 2; h++) {
                int lr = wm + mt * 16 + (lane >> 2) + h * 8;
                if (row0 + lr < count) {
                    int col = n0 + wn + j * 8 + (lane & 3) * 2;
                    size_t ob = (size_t)(hbase + row0 + lr) * DIM + col;
                    *(float2*)(g_d + ob) =
                        make_float2(acc[mt][j][h * 2], acc[mt][j][h * 2 + 1]);
                }
            }
}

// ---------------- combine: out[t] = shared + routed1 + routed2 ------------
__global__ void combine_kernel(float* __restrict__ out, int T) {
    int t = blockIdx.x;
    int r1 = g_offset[g_exp[2 * t]]     + g_pos[2 * t];
    int r2 = g_offset[g_exp[2 * t + 1]] + g_pos[2 * t + 1];
    const float4* ps = (const float4*)(g_d + (size_t)(2 * T + t) * DIM);
    const float4* p1 = (const float4*)(g_d + (size_t)r1 * DIM);
    const float4* p2 = (const float4*)(g_d + (size_t)r2 * DIM);
    float4* po = (float4*)(out + (size_t)t * DIM);
#pragma unroll
    for (int q = 0; q < 2; q++) {
        int c = threadIdx.x + q * 256;  // 512 float4 per row
        float4 a = ps[c], b = p1[c], d = p2[c];
        po[c] = make_float4(a.x + b.x + d.x, a.y + b.y + d.y,
                            a.z + b.z + d.z, a.w + b.w + d.w);
    }
}

// ---------------- entry point ----------------------------------------------
extern "C" void kernel_launch(void* const* d_in, const int* in_sizes, int n_in,
                              void* d_out, int out_size) {
    const float* x   = (const float*)d_in[0];
    const float* gw  = (const float*)d_in[1];
    const float* w1  = (const float*)d_in[2];
    const float* w3  = (const float*)d_in[3];
    const float* w2  = (const float*)d_in[4];
    const float* sw1 = (const float*)d_in[5];
    const float* sw3 = (const float*)d_in[6];
    const float* sw2 = (const float*)d_in[7];
    float* out = (float*)d_out;

    int T = in_sizes[0] / DIM;  // 4096

    const int SM = NST * STAGE;  // 96 KB
    cudaFuncSetAttribute(gemm_up,   cudaFuncAttributeMaxDynamicSharedMemorySize, SM);
    cudaFuncSetAttribute(gemm_down, cudaFuncAttributeMaxDynamicSharedMemorySize, SM);

    // lazily created once (non-captured correctness call); reused in capture
    static cudaStream_t sA = 0, sB = 0, sC = 0;
    static cudaEvent_t  evF = 0, evX = 0, evW2 = 0, evG = 0, evDS = 0;
    if (!sA) {
        cudaStreamCreateWithFlags(&sA, cudaStreamNonBlocking);
        cudaStreamCreateWithFlags(&sB, cudaStreamNonBlocking);
        cudaStreamCreateWithFlags(&sC, cudaStreamNonBlocking);
        cudaEventCreateWithFlags(&evF,  cudaEventDisableTiming);
        cudaEventCreateWithFlags(&evX,  cudaEventDisableTiming);
        cudaEventCreateWithFlags(&evW2, cudaEventDisableTiming);
        cudaEventCreateWithFlags(&evG,  cudaEventDisableTiming);
        cudaEventCreateWithFlags(&evDS, cudaEventDisableTiming);
    }

    __half *xh, *w1h, *w3h, *w2h, *s1h, *s3h, *s2h;
    cudaGetSymbolAddress((void**)&xh,  g_xh);
    cudaGetSymbolAddress((void**)&w1h, g_w1h);
    cudaGetSymbolAddress((void**)&w3h, g_w3h);
    cudaGetSymbolAddress((void**)&w2h, g_w2h);
    cudaGetSymbolAddress((void**)&s1h, g_sw1h);
    cudaGetSymbolAddress((void**)&s3h, g_sw3h);
    cudaGetSymbolAddress((void**)&s2h, g_sw2h);

    int nw4 = NE * INTER * DIM / 4;
    int ns4 = INTER * DIM / 4;
    int nx4 = T * DIM / 4;

    // fork point
    cudaEventRecord(evF, 0);

    // sA: w2/sw2 converts (needed only by down GEMMs)
    cudaStreamWaitEvent(sA, evF, 0);
    cvt_hi_kernel<<<(nw4 + 1023) / 1024, 256, 0, sA>>>((const float4*)w2, (uint2*)w2h, nw4);
    cvt_hi_kernel<<<(ns4 + 1023) / 1024, 256, 0, sA>>>((const float4*)sw2, (uint2*)s2h, ns4);
    cudaEventRecord(evW2, sA);

    // sB: gating (needed only by routed GEMMs)
    cudaStreamWaitEvent(sB, evF, 0);
    reset_kernel<<<1, 32, 0, sB>>>();
    gate_kernel<<<(T + 7) / 8, 256, 0, sB>>>(x, gw, T);
    offset_kernel<<<1, 1, 0, sB>>>();
    cudaEventRecord(evG, sB);

    // main: x + shared-up converts first (unblocks shared chain early)
    cvt_hi_kernel<<<(nx4 + 1023) / 1024, 256>>>((const float4*)x, (uint2*)xh, nx4);
    cvt_hi_kernel<<<(ns4 + 1023) / 1024, 256>>>((const float4*)sw1, (uint2*)s1h, ns4);
    cvt_hi_kernel<<<(ns4 + 1023) / 1024, 256>>>((const float4*)sw3, (uint2*)s3h, ns4);
    cudaEventRecord(evX, 0);

    // sC: shared-expert chain (no gate dependency)
    cudaStreamWaitEvent(sC, evX, 0);
    {
        dim3 gupS(INTER / 64, (T + 127) / 128, 1);
        gemm_up<<<gupS, 128, SM, sC>>>(T, NE);
        cudaStreamWaitEvent(sC, evW2, 0);
        dim3 gdnS(DIM / 128, (T + 127) / 128, 1);
        gemm_down<<<gdnS, 128, SM, sC>>>(T, NE);
        cudaEventRecord(evDS, sC);
    }

    // main: routed weight converts, then routed chain
    cvt_hi_kernel<<<(nw4 + 1023) / 1024, 256>>>((const float4*)w1, (uint2*)w1h, nw4);
    cvt_hi_kernel<<<(nw4 + 1023) / 1024, 256>>>((const float4*)w3, (uint2*)w3h, nw4);

    cudaStreamWaitEvent(0, evG, 0);
    dim3 gupR(INTER / 64, (T + 127) / 128, NE);
    gemm_up<<<gupR, 128, SM>>>(T, 0);

    cudaStreamWaitEvent(0, evW2, 0);
    dim3 gdnR(DIM / 128, (T + 127) / 128, NE);
    gemm_down<<<gdnR, 128, SM>>>(T, 0);

    cudaStreamWaitEvent(0, evDS, 0);
    combine_kernel<<<T, 256>>>(out, T);
}

// round 12
// speedup vs baseline: 1.0546x; 1.0546x over previous
#include <cuda_runtime.h>
#include <cuda_fp16.h>
#include <math.h>
#include <stdint.h>

#define DIM   2048
#define INTER 1408
#define NE    15
#define TMAX  4096
#define KC    32
// smem: A stages 4 x 8KB at [0,32K); B double-buffer 2 x 8KB at [32K,48K)
#define ASTG  8192
#define BBASE 32768
#define SMEMB 49152

// ---------------- device scratch ----------------
__device__ int   g_count[NE];
__device__ int   g_offset[NE + 1];
__device__ int   g_tok[NE * TMAX];
__device__ float g_wt[NE * TMAX];
__device__ int   g_exp[2 * TMAX];
__device__ int   g_pos[2 * TMAX];
__device__ __half g_xh[(size_t)TMAX * DIM];
__device__ __half g_hh[(size_t)3 * TMAX * INTER];
__device__ float  g_d[(size_t)3 * TMAX * DIM];   // down results, compacted rows

// ---------------- helpers ----------------
__device__ __forceinline__ uint32_t smem_u32(const void* p) {
    uint32_t a;
    asm("{ .reg .u64 t; cvta.to.shared.u64 t, %1; cvt.u32.u64 %0, t; }" : "=r"(a) : "l"(p));
    return a;
}
// swizzled byte offset inside a 128x32 fp16 tile (64B rows, 4 chunks of 16B)
__device__ __forceinline__ uint32_t toff(uint32_t r, uint32_t c) {
    return r * 64u + ((c ^ ((r >> 1) & 3u)) << 4);
}
__device__ __forceinline__ void ldsm4(uint32_t r[4], uint32_t a) {
    asm volatile("ldmatrix.sync.aligned.m8n8.x4.shared.b16 {%0,%1,%2,%3},[%4];"
                 : "=r"(r[0]), "=r"(r[1]), "=r"(r[2]), "=r"(r[3]) : "r"(a));
}
__device__ __forceinline__ void mma_f16(float c[4], const uint32_t a[4], const uint32_t b[2]) {
    asm volatile("mma.sync.aligned.m16n8k16.row.col.f32.f16.f16.f32 "
                 "{%0,%1,%2,%3},{%4,%5,%6,%7},{%8,%9},{%0,%1,%2,%3};"
                 : "+f"(c[0]), "+f"(c[1]), "+f"(c[2]), "+f"(c[3])
                 : "r"(a[0]), "r"(a[1]), "r"(a[2]), "r"(a[3]), "r"(b[0]), "r"(b[1]));
}
__device__ __forceinline__ void cpa16(uint32_t s, const void* g) {
    asm volatile("cp.async.cg.shared.global [%0], [%1], 16;" :: "r"(s), "l"(g));
}
__device__ __forceinline__ void cpcommit() { asm volatile("cp.async.commit_group;"); }
template <int N> __device__ __forceinline__ void cpwait() {
    asm volatile("cp.async.wait_group %0;" :: "n"(N));
}
__device__ __forceinline__ uint2 f4_to_h4(float4 v) {
    __half2 a = __floats2half2_rn(v.x, v.y), b = __floats2half2_rn(v.z, v.w);
    return make_uint2(*(uint32_t*)&a, *(uint32_t*)&b);
}

// one k-chunk, 32x64 warp tile: c += a*b  (A at abase, B at bbase)
__device__ __forceinline__ void compute_iter1(float acc[2][8][4], uint32_t abase,
                                              uint32_t bbase,
                                              int wm, int wn, int arow, int asel,
                                              int brow, int bsel) {
#pragma unroll
    for (int ks = 0; ks < 2; ks++) {
        uint32_t ah[2][4];
#pragma unroll
        for (int mt = 0; mt < 2; mt++) {
            uint32_t ao = toff((uint32_t)(wm + mt * 16 + arow), (uint32_t)(ks * 2 + asel));
            ldsm4(ah[mt], abase + ao);
        }
#pragma unroll
        for (int np = 0; np < 4; np++) {
            uint32_t bo = toff((uint32_t)(wn + np * 16 + brow), (uint32_t)(ks * 2 + bsel));
            uint32_t bh[4];
            ldsm4(bh, bbase + bo);
#pragma unroll
            for (int mt = 0; mt < 2; mt++)
#pragma unroll
                for (int ns = 0; ns < 2; ns++)
                    mma_f16(acc[mt][np * 2 + ns], ah[mt], bh + ns * 2);
        }
    }
}

// ---------------- x convert ----------------
__global__ void cvt_hi_kernel(const float4* __restrict__ in, uint2* __restrict__ hi, int n4) {
    int i = blockIdx.x * 1024 + threadIdx.x;
#pragma unroll
    for (int j = 0; j < 4; j++, i += 256) {
        if (i < n4) hi[i] = f4_to_h4(in[i]);
    }
}

// ---------------- gating: warp per token ----------------
__global__ void reset_kernel() { if (threadIdx.x < NE) g_count[threadIdx.x] = 0; }

__global__ void gate_kernel(const float* __restrict__ x,
                            const float* __restrict__ gw, int T) {
    int warp = threadIdx.x >> 5, lane = threadIdx.x & 31;
    int t = blockIdx.x * 8 + warp;
    if (t >= T) return;
    const float4* xt = (const float4*)(x + (size_t)t * DIM);
    const float4* gwv = (const float4*)gw;
    float acc[NE];
#pragma unroll
    for (int e = 0; e < NE; e++) acc[e] = 0.f;
    for (int k = lane; k < DIM / 4; k += 32) {
        float4 xv = xt[k];
#pragma unroll
        for (int e = 0; e < NE; e++) {
            float4 wv = gwv[e * (DIM / 4) + k];
            acc[e] += xv.x * wv.x + xv.y * wv.y + xv.z * wv.z + xv.w * wv.w;
        }
    }
#pragma unroll
    for (int e = 0; e < NE; e++)
#pragma unroll
        for (int o = 16; o > 0; o >>= 1)
            acc[e] += __shfl_xor_sync(0xffffffffu, acc[e], o);
    if (lane == 0) {
        float mx = -1e30f;
#pragma unroll
        for (int e = 0; e < NE; e++) mx = fmaxf(mx, acc[e]);
        float p[NE], sum = 0.f;
#pragma unroll
        for (int e = 0; e < NE; e++) { p[e] = expf(acc[e] - mx); sum += p[e]; }
        int i1 = 0;
        for (int e = 1; e < NE; e++) if (acc[e] > acc[i1]) i1 = e;
        int i2 = (i1 == 0) ? 1 : 0;
        for (int e = 0; e < NE; e++) if (e != i1 && acc[e] > acc[i2]) i2 = e;
        float inv = 1.f / sum;
        int idx[2] = {i1, i2};
#pragma unroll
        for (int ssel = 0; ssel < 2; ssel++) {
            int e = idx[ssel];
            int pos = atomicAdd(&g_count[e], 1);
            g_tok[e * TMAX + pos] = t;
            g_wt[e * TMAX + pos]  = p[e] * inv;
            g_exp[2 * t + ssel] = e;
            g_pos[2 * t + ssel] = pos;
        }
    }
}

__global__ void offset_kernel() {
    int s = 0;
    for (int e = 0; e < NE; e++) { g_offset[e] = s; s += g_count[e]; }
    g_offset[NE] = s;
}

// ---------------- fused up GEMM: h = silu(X W1^T)*(X W3^T)*wt -------------
// A (xh fp16) via cp.async; B (w1/w3 fp32) via LDG+cvt+STS, double-buffered.
// B tile rows [0,64)=W1 cols n0.., [64,128)=W3 same cols. Warps 0-3 -> u1,
// warps 4-7 -> u3 at identical fragment coords; epilogue exchanges u3.
// grid: (INTER/64=22, 32, nz); e = z0 + blockIdx.z; e==NE => shared expert
__global__ void __launch_bounds__(256, 2) gemm_up(
    const float* __restrict__ w1, const float* __restrict__ w3,
    const float* __restrict__ sw1, const float* __restrict__ sw3,
    int T, int z0) {
    int e = z0 + blockIdx.z;
    bool se = (e == NE);
    int count = se ? T : g_count[e];
    int row0 = blockIdx.y * 128;
    if (row0 >= count) return;
    int hbase = se ? 2 * T : g_offset[e];
    const float* W1 = se ? sw1 : w1 + (size_t)e * INTER * DIM;
    const float* W3 = se ? sw3 : w3 + (size_t)e * INTER * DIM;
    int n0 = blockIdx.x * 64;

    extern __shared__ __align__(128) char smem[];
    __shared__ int stok[128];
    __shared__ float swt[128];
    int tid = threadIdx.x, wid = tid >> 5, lane = tid & 31;
    if (tid < 128) {
        int r = row0 + tid;
        int rc = (r < count) ? r : count - 1;
        stok[tid] = se ? rc : g_tok[e * TMAX + rc];
        swt[tid]  = (se || r >= count) ? 1.f : g_wt[e * TMAX + r];
    }
    __syncthreads();

    uint32_t sb = smem_u32(smem);
    // A chunks: 512 of (row, 16B chunk)
    uint32_t soffA[2], aoff[2];
#pragma unroll
    for (int j = 0; j < 2; j++) {
        int chunk = tid + j * 256;
        int r = chunk >> 2, c4 = chunk & 3;
        soffA[j] = toff((uint32_t)r, (uint32_t)c4);
        aoff[j] = (uint32_t)stok[r] * DIM + c4 * 8;
    }
    // B: 1024 float4 chunks (128 rows x 8 float4)
    uint32_t soffB[4];
    const float* bptr[4];
#pragma unroll
    for (int j = 0; j < 4; j++) {
        int chunk = tid + j * 256;
        int r = chunk >> 3, c4f = chunk & 7;
        soffB[j] = toff((uint32_t)r, (uint32_t)(c4f >> 1)) + (uint32_t)(c4f & 1) * 8;
        bptr[j] = ((r < 64) ? (W1 + (size_t)(n0 + r) * DIM)
                            : (W3 + (size_t)(n0 + r - 64) * DIM)) + c4f * 4;
    }

    const int NIT = DIM / KC;  // 64
    auto issueA = [&](int itn) {
        if (itn < NIT) {
            uint32_t db = sb + (uint32_t)(itn & 3) * ASTG;
            int kk = itn * KC;
#pragma unroll
            for (int j = 0; j < 2; j++) cpa16(db + soffA[j], g_xh + aoff[j] + kk);
        }
        cpcommit();
    };
    float4 br[4];
    auto ldgB = [&](int itn) {
        if (itn < NIT) {
            int kk = itn * KC;
#pragma unroll
            for (int j = 0; j < 4; j++) br[j] = *(const float4*)(bptr[j] + kk);
        }
    };
    auto stsB = [&](int itn) {
        if (itn < NIT) {
            char* bb = smem + BBASE + (itn & 1) * 8192;
#pragma unroll
            for (int j = 0; j < 4; j++) *(uint2*)(bb + soffB[j]) = f4_to_h4(br[j]);
        }
    };

    // prologue
    ldgB(0); stsB(0); ldgB(1);
    issueA(0); issueA(1); issueA(2);

    int arow = lane & 15, asel = lane >> 4;
    int brow = (lane & 7) + ((lane & 16) >> 1), bsel = (lane >> 3) & 1;
    int wm = (wid & 3) * 32, wn = (wid >> 2) * 64;

    float acc[2][8][4] = {};
    for (int it = 0; it < NIT; it++) {
        cpwait<2>();
        __syncthreads();     // prior STS visible; compute(it-1) done
        stsB(it + 1);        // br holds B(it+1)
        ldgB(it + 2);
        issueA(it + 3);
        compute_iter1(acc, sb + (uint32_t)(it & 3) * ASTG,
                      sb + BBASE + (uint32_t)(it & 1) * 8192,
                      wm, wn, arow, asel, brow, bsel);
    }
    cpwait<0>();
    __syncthreads();

    // epilogue: warps 4-7 hold u3 at same (row,col) coords as warps 0-3's u1
    float* ex = (float*)smem;  // 128 x 66 fp32 exchange (33.8 KB < 48 KB)
    if (wid >= 4) {
#pragma unroll
        for (int mt = 0; mt < 2; mt++)
#pragma unroll
            for (int j = 0; j < 8; j++)
#pragma unroll
                for (int h = 0; h < 2; h++) {
                    int lr = wm + mt * 16 + (lane >> 2) + h * 8;
                    int col = j * 8 + (lane & 3) * 2;
                    ex[lr * 66 + col]     = acc[mt][j][h * 2];
                    ex[lr * 66 + col + 1] = acc[mt][j][h * 2 + 1];
                }
    }
    __syncthreads();
    if (wid < 4) {
#pragma unroll
        for (int mt = 0; mt < 2; mt++)
#pragma unroll
            for (int j = 0; j < 8; j++)
#pragma unroll
                for (int h = 0; h < 2; h++) {
                    int lr = wm + mt * 16 + (lane >> 2) + h * 8;
                    if (row0 + lr < count) {
                        int col = j * 8 + (lane & 3) * 2;
                        float wt = swt[lr];
                        float u1a = acc[mt][j][h * 2],     u3a = ex[lr * 66 + col];
                        float u1b = acc[mt][j][h * 2 + 1], u3b = ex[lr * 66 + col + 1];
                        float ha = (u1a / (1.f + expf(-u1a))) * u3a * wt;
                        float hb = (u1b / (1.f + expf(-u1b))) * u3b * wt;
                        __half2 H = __floats2half2_rn(ha, hb);
                        size_t o = (size_t)(hbase + row0 + lr) * INTER + n0 + col;
                        *(__half2*)(g_hh + o) = H;
                    }
                }
    }
}

// ---------------- down GEMM: g_d = H_hi W2^T (fp32 B direct) ---------------
// grid: (DIM/128=16, 32, nz); z = z0 + blockIdx.z; z==NE => shared expert
__global__ void __launch_bounds__(256, 2) gemm_down(
    const float* __restrict__ w2, const float* __restrict__ sw2, int T, int z0) {
    int z = z0 + blockIdx.z;
    bool se = (z == NE);
    int count = se ? T : g_count[z];
    int row0 = blockIdx.y * 128;
    if (row0 >= count) return;
    int hbase = se ? 2 * T : g_offset[z];
    const float* B = se ? sw2 : w2 + (size_t)z * DIM * INTER;
    int n0 = blockIdx.x * 128;

    extern __shared__ __align__(128) char smem[];
    int tid = threadIdx.x, wid = tid >> 5, lane = tid & 31;

    uint32_t sb = smem_u32(smem);
    uint32_t soffA[2], aoff[2];
#pragma unroll
    for (int j = 0; j < 2; j++) {
        int chunk = tid + j * 256;
        int r = chunk >> 2, c4 = chunk & 3;
        soffA[j] = toff((uint32_t)r, (uint32_t)c4);
        int rr = row0 + r;
        int hr = hbase + ((rr < count) ? rr : count - 1);
        aoff[j] = (uint32_t)hr * INTER + c4 * 8;
    }
    uint32_t soffB[4];
    const float* bptr[4];
#pragma unroll
    for (int j = 0; j < 4; j++) {
        int chunk = tid + j * 256;
        int r = chunk >> 3, c4f = chunk & 7;
        soffB[j] = toff((uint32_t)r, (uint32_t)(c4f >> 1)) + (uint32_t)(c4f & 1) * 8;
        bptr[j] = B + (size_t)(n0 + r) * INTER + c4f * 4;
    }

    const int NIT = INTER / KC;  // 44
    auto issueA = [&](int itn) {
        if (itn < NIT) {
            uint32_t db = sb + (uint32_t)(itn & 3) * ASTG;
            int kk = itn * KC;
#pragma unroll
            for (int j = 0; j < 2; j++) cpa16(db + soffA[j], g_hh + aoff[j] + kk);
        }
        cpcommit();
    };
    float4 br[4];
    auto ldgB = [&](int itn) {
        if (itn < NIT) {
            int kk = itn * KC;
#pragma unroll
            for (int j = 0; j < 4; j++) br[j] = *(const float4*)(bptr[j] + kk);
        }
    };
    auto stsB = [&](int itn) {
        if (itn < NIT) {
            char* bb = smem + BBASE + (itn & 1) * 8192;
#pragma unroll
            for (int j = 0; j < 4; j++) *(uint2*)(bb + soffB[j]) = f4_to_h4(br[j]);
        }
    };

    ldgB(0); stsB(0); ldgB(1);
    issueA(0); issueA(1); issueA(2);

    int arow = lane & 15, asel = lane >> 4;
    int brow = (lane & 7) + ((lane & 16) >> 1), bsel = (lane >> 3) & 1;
    int wm = (wid & 3) * 32, wn = (wid >> 2) * 64;

    float acc[2][8][4] = {};
    for (int it = 0; it < NIT; it++) {
        cpwait<2>();
        __syncthreads();
        stsB(it + 1);
        ldgB(it + 2);
        issueA(it + 3);
        compute_iter1(acc, sb + (uint32_t)(it & 3) * ASTG,
                      sb + BBASE + (uint32_t)(it & 1) * 8192,
                      wm, wn, arow, asel, brow, bsel);
    }

#pragma unroll
    for (int mt = 0; mt < 2; mt++)
#pragma unroll
        for (int j = 0; j < 8; j++)
#pragma unroll
            for (int h = 0; h < 2; h++) {
                int lr = wm + mt * 16 + (lane >> 2) + h * 8;
                if (row0 + lr < count) {
                    int col = n0 + wn + j * 8 + (lane & 3) * 2;
                    size_t ob = (size_t)(hbase + row0 + lr) * DIM + col;
                    *(float2*)(g_d + ob) =
                        make_float2(acc[mt][j][h * 2], acc[mt][j][h * 2 + 1]);
                }
            }
}

// ---------------- combine: out[t] = shared + routed1 + routed2 ------------
__global__ void combine_kernel(float* __restrict__ out, int T) {
    int t = blockIdx.x;
    int r1 = g_offset[g_exp[2 * t]]     + g_pos[2 * t];
    int r2 = g_offset[g_exp[2 * t + 1]] + g_pos[2 * t + 1];
    const float4* ps = (const float4*)(g_d + (size_t)(2 * T + t) * DIM);
    const float4* p1 = (const float4*)(g_d + (size_t)r1 * DIM);
    const float4* p2 = (const float4*)(g_d + (size_t)r2 * DIM);
    float4* po = (float4*)(out + (size_t)t * DIM);
#pragma unroll
    for (int q = 0; q < 2; q++) {
        int c = threadIdx.x + q * 256;  // 512 float4 per row
        float4 a = ps[c], b = p1[c], d = p2[c];
        po[c] = make_float4(a.x + b.x + d.x, a.y + b.y + d.y,
                            a.z + b.z + d.z, a.w + b.w + d.w);
    }
}

// ---------------- entry point ----------------------------------------------
extern "C" void kernel_launch(void* const* d_in, const int* in_sizes, int n_in,
                              void* d_out, int out_size) {
    const float* x   = (const float*)d_in[0];
    const float* gw  = (const float*)d_in[1];
    const float* w1  = (const float*)d_in[2];
    const float* w3  = (const float*)d_in[3];
    const float* w2  = (const float*)d_in[4];
    const float* sw1 = (const float*)d_in[5];
    const float* sw3 = (const float*)d_in[6];
    const float* sw2 = (const float*)d_in[7];
    float* out = (float*)d_out;

    int T = in_sizes[0] / DIM;  // 4096

    cudaFuncSetAttribute(gemm_up,   cudaFuncAttributeMaxDynamicSharedMemorySize, SMEMB);
    cudaFuncSetAttribute(gemm_down, cudaFuncAttributeMaxDynamicSharedMemorySize, SMEMB);

    // lazily created once (non-captured correctness call); reused in capture
    static cudaStream_t sB = 0, sC = 0;
    static cudaEvent_t  evF = 0, evX = 0, evG = 0, evDS = 0;
    if (!sB) {
        cudaStreamCreateWithFlags(&sB, cudaStreamNonBlocking);
        cudaStreamCreateWithFlags(&sC, cudaStreamNonBlocking);
        cudaEventCreateWithFlags(&evF,  cudaEventDisableTiming);
        cudaEventCreateWithFlags(&evX,  cudaEventDisableTiming);
        cudaEventCreateWithFlags(&evG,  cudaEventDisableTiming);
        cudaEventCreateWithFlags(&evDS, cudaEventDisableTiming);
    }

    __half* xh;
    cudaGetSymbolAddress((void**)&xh, g_xh);
    int nx4 = T * DIM / 4;

    // fork point
    cudaEventRecord(evF, 0);

    // sB: gating (needed only by routed GEMMs)
    cudaStreamWaitEvent(sB, evF, 0);
    reset_kernel<<<1, 32, 0, sB>>>();
    gate_kernel<<<(T + 7) / 8, 256, 0, sB>>>(x, gw, T);
    offset_kernel<<<1, 1, 0, sB>>>();
    cudaEventRecord(evG, sB);

    // main: x convert (only remaining convert)
    cvt_hi_kernel<<<(nx4 + 1023) / 1024, 256>>>((const float4*)x, (uint2*)xh, nx4);
    cudaEventRecord(evX, 0);

    // sC: shared-expert chain (no gate dependency)
    cudaStreamWaitEvent(sC, evX, 0);
    {
        dim3 gupS(INTER / 64, (T + 127) / 128, 1);
        gemm_up<<<gupS, 256, SMEMB, sC>>>(w1, w3, sw1, sw3, T, NE);
        dim3 gdnS(DIM / 128, (T + 127) / 128, 1);
        gemm_down<<<gdnS, 256, SMEMB, sC>>>(w2, sw2, T, NE);
        cudaEventRecord(evDS, sC);
    }

    // main: routed chain
    cudaStreamWaitEvent(0, evG, 0);
    dim3 gupR(INTER / 64, (T + 127) / 128, NE);
    gemm_up<<<gupR, 256, SMEMB>>>(w1, w3, sw1, sw3, T, 0);

    dim3 gdnR(DIM / 128, (T + 127) / 128, NE);
    gemm_down<<<gdnR, 256, SMEMB>>>(w2, sw2, T, 0);

    cudaStreamWaitEvent(0, evDS, 0);
    combine_kernel<<<T, 256>>>(out, T);
}

// round 13
// speedup vs baseline: 1.0619x; 1.0069x over previous
#include <cuda_runtime.h>
#include <cuda_fp16.h>
#include <math.h>
#include <stdint.h>

#define DIM   2048
#define INTER 1408
#define NE    15
#define TMAX  4096
#define KC    32
// stage layout (bytes): AH[0,8K) BH[8K,16K)
#define STAGE 16384
#define NST   6

// ---------------- device scratch ----------------
__device__ int   g_count[NE];
__device__ int   g_offset[NE + 1];
__device__ int   g_tok[NE * TMAX];
__device__ float g_wt[NE * TMAX];
__device__ int   g_exp[2 * TMAX];
__device__ int   g_pos[2 * TMAX];
__device__ __half g_xh[(size_t)TMAX * DIM];
__device__ __half g_w1h[(size_t)NE * INTER * DIM];
__device__ __half g_w3h[(size_t)NE * INTER * DIM];
__device__ __half g_w2h[(size_t)NE * DIM * INTER];
__device__ __half g_sw1h[(size_t)INTER * DIM];
__device__ __half g_sw3h[(size_t)INTER * DIM];
__device__ __half g_sw2h[(size_t)DIM * INTER];
__device__ __half g_hh[(size_t)3 * TMAX * INTER];
__device__ float  g_d[(size_t)3 * TMAX * DIM];   // down results, compacted rows

// ---------------- helpers ----------------
__device__ __forceinline__ uint32_t smem_u32(const void* p) {
    uint32_t a;
    asm("{ .reg .u64 t; cvta.to.shared.u64 t, %1; cvt.u32.u64 %0, t; }" : "=r"(a) : "l"(p));
    return a;
}
// swizzled byte offset inside a 128x32 fp16 tile (64B rows, 4 chunks of 16B)
__device__ __forceinline__ uint32_t toff(uint32_t r, uint32_t c) {
    return r * 64u + ((c ^ ((r >> 1) & 3u)) << 4);
}
__device__ __forceinline__ void ldsm4(uint32_t r[4], uint32_t a) {
    asm volatile("ldmatrix.sync.aligned.m8n8.x4.shared.b16 {%0,%1,%2,%3},[%4];"
                 : "=r"(r[0]), "=r"(r[1]), "=r"(r[2]), "=r"(r[3]) : "r"(a));
}
__device__ __forceinline__ void mma_f16(float c[4], const uint32_t a[4], const uint32_t b[2]) {
    asm volatile("mma.sync.aligned.m16n8k16.row.col.f32.f16.f16.f32 "
                 "{%0,%1,%2,%3},{%4,%5,%6,%7},{%8,%9},{%0,%1,%2,%3};"
                 : "+f"(c[0]), "+f"(c[1]), "+f"(c[2]), "+f"(c[3])
                 : "r"(a[0]), "r"(a[1]), "r"(a[2]), "r"(a[3]), "r"(b[0]), "r"(b[1]));
}
__device__ __forceinline__ void cpa16(uint32_t s, const void* g) {
    asm volatile("cp.async.cg.shared.global [%0], [%1], 16;" :: "r"(s), "l"(g));
}
__device__ __forceinline__ void cpcommit() { asm volatile("cp.async.commit_group;"); }
template <int N> __device__ __forceinline__ void cpwait() {
    asm volatile("cp.async.wait_group %0;" :: "n"(N));
}
__device__ __forceinline__ uint32_t f2_to_h2(float x, float y) {
    __half2 h = __floats2half2_rn(x, y);
    return *(uint32_t*)&h;
}

// one k-chunk, 1-term: c += ah*bh
__device__ __forceinline__ void compute_iter1(float acc[2][8][4], uint32_t base,
                                              int wm, int wn, int arow, int asel,
                                              int brow, int bsel) {
#pragma unroll
    for (int ks = 0; ks < 2; ks++) {
        uint32_t ah[2][4];
#pragma unroll
        for (int mt = 0; mt < 2; mt++) {
            uint32_t ao = toff((uint32_t)(wm + mt * 16 + arow), (uint32_t)(ks * 2 + asel));
            ldsm4(ah[mt], base + ao);
        }
#pragma unroll
        for (int np = 0; np < 4; np++) {
            uint32_t bo = toff((uint32_t)(wn + np * 16 + brow), (uint32_t)(ks * 2 + bsel));
            uint32_t bh[4];
            ldsm4(bh, base + 8192 + bo);
#pragma unroll
            for (int mt = 0; mt < 2; mt++)
#pragma unroll
                for (int ns = 0; ns < 2; ns++)
                    mma_f16(acc[mt][np * 2 + ns], ah[mt], bh + ns * 2);
        }
    }
}

// ---------------- fused converts: up to 3 (src,dst,n8) pairs ---------------
// n8 = element count / 8 (each output is one uint4 = 8 fp16, from 2 float4)
__global__ void cvt3_kernel(const float4* __restrict__ s0, uint4* __restrict__ d0, int n0,
                            const float4* __restrict__ s1, uint4* __restrict__ d1, int n1,
                            const float4* __restrict__ s2, uint4* __restrict__ d2, int n2) {
    int base = blockIdx.x * 1024 + threadIdx.x;
#pragma unroll
    for (int j = 0; j < 4; j++) {
        int i = base + j * 256;
        if (i < n0) {
            float4 a = s0[2 * i], b = s0[2 * i + 1];
            d0[i] = make_uint4(f2_to_h2(a.x, a.y), f2_to_h2(a.z, a.w),
                               f2_to_h2(b.x, b.y), f2_to_h2(b.z, b.w));
        }
        if (i < n1) {
            float4 a = s1[2 * i], b = s1[2 * i + 1];
            d1[i] = make_uint4(f2_to_h2(a.x, a.y), f2_to_h2(a.z, a.w),
                               f2_to_h2(b.x, b.y), f2_to_h2(b.z, b.w));
        }
        if (i < n2) {
            float4 a = s2[2 * i], b = s2[2 * i + 1];
            d2[i] = make_uint4(f2_to_h2(a.x, a.y), f2_to_h2(a.z, a.w),
                               f2_to_h2(b.x, b.y), f2_to_h2(b.z, b.w));
        }
    }
}

// ---------------- gating: warp per token ----------------
__global__ void reset_kernel() { if (threadIdx.x < NE) g_count[threadIdx.x] = 0; }

__global__ void gate_kernel(const float* __restrict__ x,
                            const float* __restrict__ gw, int T) {
    int warp = threadIdx.x >> 5, lane = threadIdx.x & 31;
    int t = blockIdx.x * 8 + warp;
    if (t >= T) return;
    const float4* xt = (const float4*)(x + (size_t)t * DIM);
    const float4* gwv = (const float4*)gw;
    float acc[NE];
#pragma unroll
    for (int e = 0; e < NE; e++) acc[e] = 0.f;
    for (int k = lane; k < DIM / 4; k += 32) {
        float4 xv = xt[k];
#pragma unroll
        for (int e = 0; e < NE; e++) {
            float4 wv = gwv[e * (DIM / 4) + k];
            acc[e] += xv.x * wv.x + xv.y * wv.y + xv.z * wv.z + xv.w * wv.w;
        }
    }
#pragma unroll
    for (int e = 0; e < NE; e++)
#pragma unroll
        for (int o = 16; o > 0; o >>= 1)
            acc[e] += __shfl_xor_sync(0xffffffffu, acc[e], o);
    if (lane == 0) {
        float mx = -1e30f;
#pragma unroll
        for (int e = 0; e < NE; e++) mx = fmaxf(mx, acc[e]);
        float p[NE], sum = 0.f;
#pragma unroll
        for (int e = 0; e < NE; e++) { p[e] = expf(acc[e] - mx); sum += p[e]; }
        int i1 = 0;
        for (int e = 1; e < NE; e++) if (acc[e] > acc[i1]) i1 = e;
        int i2 = (i1 == 0) ? 1 : 0;
        for (int e = 0; e < NE; e++) if (e != i1 && acc[e] > acc[i2]) i2 = e;
        float inv = 1.f / sum;
        int idx[2] = {i1, i2};
#pragma unroll
        for (int ssel = 0; ssel < 2; ssel++) {
            int e = idx[ssel];
            int pos = atomicAdd(&g_count[e], 1);
            g_tok[e * TMAX + pos] = t;
            g_wt[e * TMAX + pos]  = p[e] * inv;
            g_exp[2 * t + ssel] = e;
            g_pos[2 * t + ssel] = pos;
        }
    }
}

__global__ void offset_kernel() {
    int s = 0;
    for (int e = 0; e < NE; e++) { g_offset[e] = s; s += g_count[e]; }
    g_offset[NE] = s;
}

// ---------------- fused up GEMM: h = silu(X W1^T)*(X W3^T)*wt -------------
// grid: (INTER/64=22, 32, nz); e = z0 + blockIdx.z; e==NE => shared expert
__global__ void __launch_bounds__(256, 2) gemm_up(int T, int z0) {
    int e = z0 + blockIdx.z;
    bool se = (e == NE);
    int count = se ? T : g_count[e];
    int row0 = blockIdx.y * 128;
    if (row0 >= count) return;
    int hbase = se ? 2 * T : g_offset[e];
    const __half* W1h = se ? g_sw1h : g_w1h + (size_t)e * INTER * DIM;
    const __half* W3h = se ? g_sw3h : g_w3h + (size_t)e * INTER * DIM;
    int n0 = blockIdx.x * 64;

    extern __shared__ __align__(128) char smem[];
    __shared__ int stok[128];
    __shared__ float swt[128];
    int tid = threadIdx.x, wid = tid >> 5, lane = tid & 31;
    if (tid < 128) {
        int r = row0 + tid;
        int rc = (r < count) ? r : count - 1;
        stok[tid] = se ? rc : g_tok[e * TMAX + rc];
        swt[tid]  = (se || r >= count) ? 1.f : g_wt[e * TMAX + r];
    }
    __syncthreads();

    uint32_t sb = smem_u32(smem);
    uint32_t soff[2], aoff[2];
    const __half* bptr[2];
#pragma unroll
    for (int j = 0; j < 2; j++) {
        int chunk = tid + j * 256;
        int r = chunk >> 2, c4 = chunk & 3;
        soff[j] = toff((uint32_t)r, (uint32_t)c4);
        aoff[j] = (uint32_t)stok[r] * DIM + c4 * 8;
        bptr[j] = ((r < 64) ? (W1h + (size_t)(n0 + r) * DIM)
                            : (W3h + (size_t)(n0 + r - 64) * DIM)) + c4 * 8;
    }

    const int NIT = DIM / KC;  // 64 (even)
    auto issue = [&](int itn) {
        if (itn < NIT) {
            uint32_t db = sb + (uint32_t)(itn % NST) * STAGE;
            int kk = itn * KC;
#pragma unroll
            for (int j = 0; j < 2; j++) {
                cpa16(db + soff[j],        g_xh + aoff[j] + kk);
                cpa16(db + 8192 + soff[j], bptr[j] + kk);
            }
        }
        cpcommit();
    };
    issue(0); issue(1); issue(2); issue(3);

    int arow = lane & 15, asel = lane >> 4;
    int brow = (lane & 7) + ((lane & 16) >> 1), bsel = (lane >> 3) & 1;
    int wm = (wid & 3) * 32, wn = (wid >> 2) * 64;

    float acc[2][8][4] = {};
    for (int it = 0; it < NIT; it += 2) {
        cpwait<2>();
        __syncthreads();
        issue(it + 4);
        issue(it + 5);
        compute_iter1(acc, sb + (uint32_t)(it % NST) * STAGE,
                      wm, wn, arow, asel, brow, bsel);
        compute_iter1(acc, sb + (uint32_t)((it + 1) % NST) * STAGE,
                      wm, wn, arow, asel, brow, bsel);
    }
    cpwait<0>();
    __syncthreads();

    // epilogue: warps 4-7 hold u3 at same (row,col) coords as warps 0-3's u1
    float* ex = (float*)smem;  // 128 x 66 fp32 exchange (33.8 KB < 96 KB)
    if (wid >= 4) {
#pragma unroll
        for (int mt = 0; mt < 2; mt++)
#pragma unroll
            for (int j = 0; j < 8; j++)
#pragma unroll
                for (int h = 0; h < 2; h++) {
                    int lr = wm + mt * 16 + (lane >> 2) + h * 8;
                    int col = j * 8 + (lane & 3) * 2;
                    ex[lr * 66 + col]     = acc[mt][j][h * 2];
                    ex[lr * 66 + col + 1] = acc[mt][j][h * 2 + 1];
                }
    }
    __syncthreads();
    if (wid < 4) {
#pragma unroll
        for (int mt = 0; mt < 2; mt++)
#pragma unroll
            for (int j = 0; j < 8; j++)
#pragma unroll
                for (int h = 0; h < 2; h++) {
                    int lr = wm + mt * 16 + (lane >> 2) + h * 8;
                    if (row0 + lr < count) {
                        int col = j * 8 + (lane & 3) * 2;
                        float wt = swt[lr];
                        float u1a = acc[mt][j][h * 2],     u3a = ex[lr * 66 + col];
                        float u1b = acc[mt][j][h * 2 + 1], u3b = ex[lr * 66 + col + 1];
                        float ha = (u1a / (1.f + expf(-u1a))) * u3a * wt;
                        float hb = (u1b / (1.f + expf(-u1b))) * u3b * wt;
                        __half2 H = __floats2half2_rn(ha, hb);
                        size_t o = (size_t)(hbase + row0 + lr) * INTER + n0 + col;
                        *(__half2*)(g_hh + o) = H;
                    }
                }
    }
}

// ---------------- down GEMM: g_d = H_hi W2h^T -------------------------------
// grid: (DIM/128=16, 32, nz); z = z0 + blockIdx.z; z==NE => shared expert
__global__ void __launch_bounds__(256, 2) gemm_down(int T, int z0) {
    int z = z0 + blockIdx.z;
    bool se = (z == NE);
    int count = se ? T : g_count[z];
    int row0 = blockIdx.y * 128;
    if (row0 >= count) return;
    int hbase = se ? 2 * T : g_offset[z];
    const __half* Bh = se ? g_sw2h : g_w2h + (size_t)z * DIM * INTER;
    int n0 = blockIdx.x * 128;

    extern __shared__ __align__(128) char smem[];
    int tid = threadIdx.x, wid = tid >> 5, lane = tid & 31;

    uint32_t sb = smem_u32(smem);
    uint32_t soff[2], aoff[2];
    const __half* bptr[2];
#pragma unroll
    for (int j = 0; j < 2; j++) {
        int chunk = tid + j * 256;
        int r = chunk >> 2, c4 = chunk & 3;
        soff[j] = toff((uint32_t)r, (uint32_t)c4);
        int rr = row0 + r;
        int hr = hbase + ((rr < count) ? rr : count - 1);
        aoff[j] = (uint32_t)hr * INTER + c4 * 8;
        bptr[j] = Bh + (size_t)(n0 + r) * INTER + c4 * 8;
    }

    const int NIT = INTER / KC;  // 44 (even)
    auto issue = [&](int itn) {
        if (itn < NIT) {
            uint32_t db = sb + (uint32_t)(itn % NST) * STAGE;
            int kk = itn * KC;
#pragma unroll
            for (int j = 0; j < 2; j++) {
                cpa16(db + soff[j],        g_hh + aoff[j] + kk);
                cpa16(db + 8192 + soff[j], bptr[j] + kk);
            }
        }
        cpcommit();
    };
    issue(0); issue(1); issue(2); issue(3);

    int arow = lane & 15, asel = lane >> 4;
    int brow = (lane & 7) + ((lane & 16) >> 1), bsel = (lane >> 3) & 1;
    int wm = (wid & 3) * 32, wn = (wid >> 2) * 64;

    float acc[2][8][4] = {};
    for (int it = 0; it < NIT; it += 2) {
        cpwait<2>();
        __syncthreads();
        issue(it + 4);
        issue(it + 5);
        compute_iter1(acc, sb + (uint32_t)(it % NST) * STAGE,
                      wm, wn, arow, asel, brow, bsel);
        compute_iter1(acc, sb + (uint32_t)((it + 1) % NST) * STAGE,
                      wm, wn, arow, asel, brow, bsel);
    }

#pragma unroll
    for (int mt = 0; mt < 2; mt++)
#pragma unroll
        for (int j = 0; j < 8; j++)
#pragma unroll
            for (int h = 0; h < 2; h++) {
                int lr = wm + mt * 16 + (lane >> 2) + h * 8;
                if (row0 + lr < count) {
                    int col = n0 + wn + j * 8 + (lane & 3) * 2;
                    size_t ob = (size_t)(hbase + row0 + lr) * DIM + col;
                    *(float2*)(g_d + ob) =
                        make_float2(acc[mt][j][h * 2], acc[mt][j][h * 2 + 1]);
                }
            }
}

// ---------------- combine: out[t] = shared + routed1 + routed2 ------------
__global__ void combine_kernel(float* __restrict__ out, int T) {
    int t = blockIdx.x;
    int r1 = g_offset[g_exp[2 * t]]     + g_pos[2 * t];
    int r2 = g_offset[g_exp[2 * t + 1]] + g_pos[2 * t + 1];
    const float4* ps = (const float4*)(g_d + (size_t)(2 * T + t) * DIM);
    const float4* p1 = (const float4*)(g_d + (size_t)r1 * DIM);
    const float4* p2 = (const float4*)(g_d + (size_t)r2 * DIM);
    float4* po = (float4*)(out + (size_t)t * DIM);
#pragma unroll
    for (int q = 0; q < 2; q++) {
        int c = threadIdx.x + q * 256;  // 512 float4 per row
        float4 a = ps[c], b = p1[c], d = p2[c];
        po[c] = make_float4(a.x + b.x + d.x, a.y + b.y + d.y,
                            a.z + b.z + d.z, a.w + b.w + d.w);
    }
}

// ---------------- entry point ----------------------------------------------
extern "C" void kernel_launch(void* const* d_in, const int* in_sizes, int n_in,
                              void* d_out, int out_size) {
    const float* x   = (const float*)d_in[0];
    const float* gw  = (const float*)d_in[1];
    const float* w1  = (const float*)d_in[2];
    const float* w3  = (const float*)d_in[3];
    const float* w2  = (const float*)d_in[4];
    const float* sw1 = (const float*)d_in[5];
    const float* sw3 = (const float*)d_in[6];
    const float* sw2 = (const float*)d_in[7];
    float* out = (float*)d_out;

    int T = in_sizes[0] / DIM;  // 4096

    const int SM = NST * STAGE;  // 96 KB
    cudaFuncSetAttribute(gemm_up,   cudaFuncAttributeMaxDynamicSharedMemorySize, SM);
    cudaFuncSetAttribute(gemm_down, cudaFuncAttributeMaxDynamicSharedMemorySize, SM);

    // lazily created once (non-captured correctness call); reused in capture
    static cudaStream_t sA = 0, sB = 0, sC = 0;
    static cudaEvent_t  evF = 0, evX = 0, evW2 = 0, evG = 0, evDS = 0;
    if (!sA) {
        cudaStreamCreateWithFlags(&sA, cudaStreamNonBlocking);
        cudaStreamCreateWithFlags(&sB, cudaStreamNonBlocking);
        cudaStreamCreateWithFlags(&sC, cudaStreamNonBlocking);
        cudaEventCreateWithFlags(&evF,  cudaEventDisableTiming);
        cudaEventCreateWithFlags(&evX,  cudaEventDisableTiming);
        cudaEventCreateWithFlags(&evW2, cudaEventDisableTiming);
        cudaEventCreateWithFlags(&evG,  cudaEventDisableTiming);
        cudaEventCreateWithFlags(&evDS, cudaEventDisableTiming);
    }

    __half *xh, *w1h, *w3h, *w2h, *s1h, *s3h, *s2h;
    cudaGetSymbolAddress((void**)&xh,  g_xh);
    cudaGetSymbolAddress((void**)&w1h, g_w1h);
    cudaGetSymbolAddress((void**)&w3h, g_w3h);
    cudaGetSymbolAddress((void**)&w2h, g_w2h);
    cudaGetSymbolAddress((void**)&s1h, g_sw1h);
    cudaGetSymbolAddress((void**)&s3h, g_sw3h);
    cudaGetSymbolAddress((void**)&s2h, g_sw2h);

    int nw8 = NE * INTER * DIM / 8;   // 5,406,720
    int ns8 = INTER * DIM / 8;        // 360,448
    int nx8 = T * DIM / 8;            // 1,048,576

    // fork point
    cudaEventRecord(evF, 0);

    // sA: w2/sw2 converts (needed only by down GEMMs)
    cudaStreamWaitEvent(sA, evF, 0);
    cvt3_kernel<<<(nw8 + 1023) / 1024, 256, 0, sA>>>(
        (const float4*)w2, (uint4*)w2h, nw8,
        (const float4*)sw2, (uint4*)s2h, ns8,
        (const float4*)0, (uint4*)0, 0);
    cudaEventRecord(evW2, sA);

    // sB: gating (needed only by routed GEMMs)
    cudaStreamWaitEvent(sB, evF, 0);
    reset_kernel<<<1, 32, 0, sB>>>();
    gate_kernel<<<(T + 7) / 8, 256, 0, sB>>>(x, gw, T);
    offset_kernel<<<1, 1, 0, sB>>>();
    cudaEventRecord(evG, sB);

    // main: x + shared-up converts first (unblocks shared chain early)
    cvt3_kernel<<<(nx8 + 1023) / 1024, 256>>>(
        (const float4*)x, (uint4*)xh, nx8,
        (const float4*)sw1, (uint4*)s1h, ns8,
        (const float4*)sw3, (uint4*)s3h, ns8);
    cudaEventRecord(evX, 0);

    // sC: shared-expert chain (no gate dependency)
    cudaStreamWaitEvent(sC, evX, 0);
    {
        dim3 gupS(INTER / 64, (T + 127) / 128, 1);
        gemm_up<<<gupS, 256, SM, sC>>>(T, NE);
        cudaStreamWaitEvent(sC, evW2, 0);
        dim3 gdnS(DIM / 128, (T + 127) / 128, 1);
        gemm_down<<<gdnS, 256, SM, sC>>>(T, NE);
        cudaEventRecord(evDS, sC);
    }

    // main: routed weight converts, then routed chain
    cvt3_kernel<<<(nw8 + 1023) / 1024, 256>>>(
        (const float4*)w1, (uint4*)w1h, nw8,
        (const float4*)w3, (uint4*)w3h, nw8,
        (const float4*)0, (uint4*)0, 0);

    cudaStreamWaitEvent(0, evG, 0);
    dim3 gupR(INTER / 64, (T + 127) / 128, NE);
    gemm_up<<<gupR, 256, SM>>>(T, 0);

    cudaStreamWaitEvent(0, evW2, 0);
    dim3 gdnR(DIM / 128, (T + 127) / 128, NE);
    gemm_down<<<gdnR, 256, SM>>>(T, 0);

    cudaStreamWaitEvent(0, evDS, 0);
    combine_kernel<<<T, 256>>>(out, T);
}

// round 14
// speedup vs baseline: 1.0800x; 1.0170x over previous
#include <cuda_runtime.h>
#include <cuda_fp16.h>
#include <math.h>
#include <stdint.h>

#define DIM   2048
#define INTER 1408
#define NE    15
#define TMAX  4096
#define KC    32
// stage layout (bytes): A[0,8K) B[8K,16K)
#define STAGE 16384
#define NST   4
#define NBU   22        // up n-blocks (64 cols of W1+W3 each)
#define NBD   16        // down n-blocks (128 cols of W2)
#define KCU   64        // up k-chunks
#define KCD   44        // down k-chunks

// ---------------- device scratch ----------------
__device__ int   g_count[NE];
__device__ int   g_offset[NE + 1];
__device__ int   g_tok[NE * TMAX];
__device__ float g_wt[NE * TMAX];
__device__ int   g_exp[2 * TMAX];
__device__ int   g_pos[2 * TMAX];
__device__ __half g_xh[(size_t)TMAX * DIM];
__device__ __half g_hh[(size_t)3 * TMAX * INTER];
__device__ float  g_d[(size_t)3 * TMAX * DIM];
// pre-swizzled weight panels: 8KB tile per (expert, nblock, kchunk)
__device__ __align__(256) __half g_wup[(size_t)(NE + 1) * NBU * KCU * 4096];
__device__ __align__(256) __half g_wdn[(size_t)(NE + 1) * NBD * KCD * 4096];

// ---------------- helpers ----------------
__device__ __forceinline__ uint32_t smem_u32(const void* p) {
    uint32_t a;
    asm("{ .reg .u64 t; cvta.to.shared.u64 t, %1; cvt.u32.u64 %0, t; }" : "=r"(a) : "l"(p));
    return a;
}
// swizzled byte offset inside a 128(or 256)x32 fp16 tile (64B rows)
__device__ __forceinline__ uint32_t toff(uint32_t r, uint32_t c) {
    return r * 64u + ((c ^ ((r >> 1) & 3u)) << 4);
}
__device__ __forceinline__ void ldsm4(uint32_t r[4], uint32_t a) {
    asm volatile("ldmatrix.sync.aligned.m8n8.x4.shared.b16 {%0,%1,%2,%3},[%4];"
                 : "=r"(r[0]), "=r"(r[1]), "=r"(r[2]), "=r"(r[3]) : "r"(a));
}
__device__ __forceinline__ void mma_f16(float c[4], const uint32_t a[4], const uint32_t b[2]) {
    asm volatile("mma.sync.aligned.m16n8k16.row.col.f32.f16.f16.f32 "
                 "{%0,%1,%2,%3},{%4,%5,%6,%7},{%8,%9},{%0,%1,%2,%3};"
                 : "+f"(c[0]), "+f"(c[1]), "+f"(c[2]), "+f"(c[3])
                 : "r"(a[0]), "r"(a[1]), "r"(a[2]), "r"(a[3]), "r"(b[0]), "r"(b[1]));
}
__device__ __forceinline__ void cpa16(uint32_t s, const void* g) {
    asm volatile("cp.async.cg.shared.global [%0], [%1], 16;" :: "r"(s), "l"(g));
}
__device__ __forceinline__ void cpcommit() { asm volatile("cp.async.commit_group;"); }
template <int N> __device__ __forceinline__ void cpwait() {
    asm volatile("cp.async.wait_group %0;" :: "n"(N));
}
__device__ __forceinline__ uint32_t f2_to_h2(float x, float y) {
    __half2 h = __floats2half2_rn(x, y);
    return *(uint32_t*)&h;
}
__device__ __forceinline__ void mbar_init(uint32_t a, uint32_t cnt) {
    asm volatile("mbarrier.init.shared.b64 [%0], %1;" :: "r"(a), "r"(cnt) : "memory");
}
__device__ __forceinline__ void mbar_expect_tx(uint32_t a, uint32_t tx) {
    asm volatile("mbarrier.arrive.expect_tx.shared.b64 _, [%0], %1;"
                 :: "r"(a), "r"(tx) : "memory");
}
__device__ __forceinline__ void bulk_g2s(uint32_t dst, const void* src, uint32_t bytes,
                                         uint32_t bar) {
    asm volatile("cp.async.bulk.shared::cta.global.mbarrier::complete_tx::bytes "
                 "[%0], [%1], %2, [%3];"
                 :: "r"(dst), "l"(src), "r"(bytes), "r"(bar) : "memory");
}
__device__ __forceinline__ void mbar_wait(uint32_t a, uint32_t parity) {
    asm volatile(
        "{\n\t.reg .pred P;\n"
        "W%=:\n\tmbarrier.try_wait.parity.shared.b64 P, [%0], %1;\n"
        "\t@!P bra W%=;\n\t}" :: "r"(a), "r"(parity) : "memory");
}

// one k-chunk, 32x64 warp tile: c += a*b (A at base, B at base+8192)
__device__ __forceinline__ void compute_iter1(float acc[2][8][4], uint32_t base,
                                              int wm, int wn, int arow, int asel,
                                              int brow, int bsel) {
#pragma unroll
    for (int ks = 0; ks < 2; ks++) {
        uint32_t ah[2][4];
#pragma unroll
        for (int mt = 0; mt < 2; mt++) {
            uint32_t ao = toff((uint32_t)(wm + mt * 16 + arow), (uint32_t)(ks * 2 + asel));
            ldsm4(ah[mt], base + ao);
        }
#pragma unroll
        for (int np = 0; np < 4; np++) {
            uint32_t bo = toff((uint32_t)(wn + np * 16 + brow), (uint32_t)(ks * 2 + bsel));
            uint32_t bh[4];
            ldsm4(bh, base + 8192 + bo);
#pragma unroll
            for (int mt = 0; mt < 2; mt++)
#pragma unroll
                for (int ns = 0; ns < 2; ns++)
                    mma_f16(acc[mt][np * 2 + ns], ah[mt], bh + ns * 2);
        }
    }
}

// ---------------- x convert ----------------
__global__ void cvt_x(const float4* __restrict__ in, uint4* __restrict__ hi, int n8) {
    int i = blockIdx.x * 1024 + threadIdx.x;
#pragma unroll
    for (int j = 0; j < 4; j++, i += 256) {
        if (i < n8) {
            float4 a = in[2 * i], b = in[2 * i + 1];
            hi[i] = make_uint4(f2_to_h2(a.x, a.y), f2_to_h2(a.z, a.w),
                               f2_to_h2(b.x, b.y), f2_to_h2(b.z, b.w));
        }
    }
}

// ---------------- weight pack: fp32 -> swizzled contiguous 8KB fp16 tiles ---
// up: tile rows [0,64)=W1 rows nb*64.., [64,128)=W3 same; grid (22, 64, NE+1)
__global__ void pack_up(const float* __restrict__ w1, const float* __restrict__ w3,
                        const float* __restrict__ sw1, const float* __restrict__ sw3) {
    int e = blockIdx.z;
    bool se = (e == NE);
    const float* W1 = se ? sw1 : w1 + (size_t)e * INTER * DIM;
    const float* W3 = se ? sw3 : w3 + (size_t)e * INTER * DIM;
    int nb = blockIdx.x, kc = blockIdx.y;
    char* tile = (char*)g_wup + (((size_t)e * NBU + nb) * KCU + kc) * 8192;
    int tid = threadIdx.x;
#pragma unroll
    for (int j = 0; j < 2; j++) {
        int chunk = tid + j * 256;
        int r = chunk >> 2, c4 = chunk & 3;
        const float* src = ((r < 64) ? W1 + (size_t)(nb * 64 + r) * DIM
                                     : W3 + (size_t)(nb * 64 + r - 64) * DIM)
                           + kc * KC + c4 * 8;
        float4 a = *(const float4*)src, b = *(const float4*)(src + 4);
        *(uint4*)(tile + toff((uint32_t)r, (uint32_t)c4)) =
            make_uint4(f2_to_h2(a.x, a.y), f2_to_h2(a.z, a.w),
                       f2_to_h2(b.x, b.y), f2_to_h2(b.z, b.w));
    }
}
// down: tile rows = 128 rows of W2; grid (16, 44, NE+1)
__global__ void pack_dn(const float* __restrict__ w2, const float* __restrict__ sw2) {
    int e = blockIdx.z;
    bool se = (e == NE);
    const float* W2 = se ? sw2 : w2 + (size_t)e * DIM * INTER;
    int nb = blockIdx.x, kc = blockIdx.y;
    char* tile = (char*)g_wdn + (((size_t)e * NBD + nb) * KCD + kc) * 8192;
    int tid = threadIdx.x;
#pragma unroll
    for (int j = 0; j < 2; j++) {
        int chunk = tid + j * 256;
        int r = chunk >> 2, c4 = chunk & 3;
        const float* src = W2 + (size_t)(nb * 128 + r) * INTER + kc * KC + c4 * 8;
        float4 a = *(const float4*)src, b = *(const float4*)(src + 4);
        *(uint4*)(tile + toff((uint32_t)r, (uint32_t)c4)) =
            make_uint4(f2_to_h2(a.x, a.y), f2_to_h2(a.z, a.w),
                       f2_to_h2(b.x, b.y), f2_to_h2(b.z, b.w));
    }
}

// ---------------- gating: warp per token ----------------
__global__ void reset_kernel() { if (threadIdx.x < NE) g_count[threadIdx.x] = 0; }

__global__ void gate_kernel(const float* __restrict__ x,
                            const float* __restrict__ gw, int T) {
    int warp = threadIdx.x >> 5, lane = threadIdx.x & 31;
    int t = blockIdx.x * 8 + warp;
    if (t >= T) return;
    const float4* xt = (const float4*)(x + (size_t)t * DIM);
    const float4* gwv = (const float4*)gw;
    float acc[NE];
#pragma unroll
    for (int e = 0; e < NE; e++) acc[e] = 0.f;
    for (int k = lane; k < DIM / 4; k += 32) {
        float4 xv = xt[k];
#pragma unroll
        for (int e = 0; e < NE; e++) {
            float4 wv = gwv[e * (DIM / 4) + k];
            acc[e] += xv.x * wv.x + xv.y * wv.y + xv.z * wv.z + xv.w * wv.w;
        }
    }
#pragma unroll
    for (int e = 0; e < NE; e++)
#pragma unroll
        for (int o = 16; o > 0; o >>= 1)
            acc[e] += __shfl_xor_sync(0xffffffffu, acc[e], o);
    if (lane == 0) {
        float mx = -1e30f;
#pragma unroll
        for (int e = 0; e < NE; e++) mx = fmaxf(mx, acc[e]);
        float p[NE], sum = 0.f;
#pragma unroll
        for (int e = 0; e < NE; e++) { p[e] = expf(acc[e] - mx); sum += p[e]; }
        int i1 = 0;
        for (int e = 1; e < NE; e++) if (acc[e] > acc[i1]) i1 = e;
        int i2 = (i1 == 0) ? 1 : 0;
        for (int e = 0; e < NE; e++) if (e != i1 && acc[e] > acc[i2]) i2 = e;
        float inv = 1.f / sum;
        int idx[2] = {i1, i2};
#pragma unroll
        for (int ssel = 0; ssel < 2; ssel++) {
            int e = idx[ssel];
            int pos = atomicAdd(&g_count[e], 1);
            g_tok[e * TMAX + pos] = t;
            g_wt[e * TMAX + pos]  = p[e] * inv;
            g_exp[2 * t + ssel] = e;
            g_pos[2 * t + ssel] = pos;
        }
    }
}

__global__ void offset_kernel() {
    int s = 0;
    for (int e = 0; e < NE; e++) { g_offset[e] = s; s += g_count[e]; }
    g_offset[NE] = s;
}

// ---------------- fused up GEMM: h = silu(X W1^T)*(X W3^T)*wt -------------
// A via cp.async from g_xh; B via cp.async.bulk from packed panel + mbarrier.
// grid: (NBU=22, 32, NE+1); e==NE => shared expert
__global__ void __launch_bounds__(256, 2) gemm_up(int T) {
    int e = blockIdx.z;
    bool se = (e == NE);
    int count = se ? T : g_count[e];
    int row0 = blockIdx.y * 128;
    if (row0 >= count) return;
    int hbase = se ? 2 * T : g_offset[e];
    const char* pan = (const char*)g_wup + ((size_t)e * NBU + blockIdx.x) * KCU * 8192;
    int n0 = blockIdx.x * 64;

    extern __shared__ __align__(128) char smem[];
    __shared__ int stok[128];
    __shared__ float swt[128];
    __shared__ __align__(8) uint64_t bars[NST];
    int tid = threadIdx.x, wid = tid >> 5, lane = tid & 31;
    if (tid < 128) {
        int r = row0 + tid;
        int rc = (r < count) ? r : count - 1;
        stok[tid] = se ? rc : g_tok[e * TMAX + rc];
        swt[tid]  = (se || r >= count) ? 1.f : g_wt[e * TMAX + r];
    }
    uint32_t bar0 = smem_u32(bars);
    if (tid == 0) {
#pragma unroll
        for (int s = 0; s < NST; s++) mbar_init(bar0 + s * 8, 1);
    }
    __syncthreads();

    uint32_t sb = smem_u32(smem);
    uint32_t soff[2], aoff[2];
#pragma unroll
    for (int j = 0; j < 2; j++) {
        int chunk = tid + j * 256;
        int r = chunk >> 2, c4 = chunk & 3;
        soff[j] = toff((uint32_t)r, (uint32_t)c4);
        aoff[j] = (uint32_t)stok[r] * DIM + c4 * 8;
    }

    const int NIT = KCU;  // 64
    auto issueA = [&](int itn) {
        if (itn < NIT) {
            uint32_t db = sb + (uint32_t)(itn & (NST - 1)) * STAGE;
            int kk = itn * KC;
#pragma unroll
            for (int j = 0; j < 2; j++) cpa16(db + soff[j], g_xh + aoff[j] + kk);
        }
        cpcommit();
    };
    auto issueB = [&](int itn) {
        if (tid == 0 && itn < NIT) {
            uint32_t bb = bar0 + (uint32_t)(itn & (NST - 1)) * 8;
            mbar_expect_tx(bb, 8192);
            bulk_g2s(sb + (uint32_t)(itn & (NST - 1)) * STAGE + 8192,
                     pan + (size_t)itn * 8192, 8192, bb);
        }
    };
    issueB(0); issueB(1); issueB(2);
    issueA(0); issueA(1); issueA(2);

    int arow = lane & 15, asel = lane >> 4;
    int brow = (lane & 7) + ((lane & 16) >> 1), bsel = (lane >> 3) & 1;
    int wm = (wid & 3) * 32, wn = (wid >> 2) * 64;

    float acc[2][8][4] = {};
    for (int it = 0; it < NIT; it++) {
        cpwait<2>();
        mbar_wait(bar0 + (uint32_t)(it & (NST - 1)) * 8, (it >> 2) & 1);
        __syncthreads();
        issueB(it + 3);
        issueA(it + 3);
        compute_iter1(acc, sb + (uint32_t)(it & (NST - 1)) * STAGE,
                      wm, wn, arow, asel, brow, bsel);
    }
    cpwait<0>();
    __syncthreads();

    // epilogue: warps 4-7 hold u3 at same (row,col) coords as warps 0-3's u1
    float* ex = (float*)smem;  // 128 x 66 fp32 exchange (33.8 KB < 64 KB)
    if (wid >= 4) {
#pragma unroll
        for (int mt = 0; mt < 2; mt++)
#pragma unroll
            for (int j = 0; j < 8; j++)
#pragma unroll
                for (int h = 0; h < 2; h++) {
                    int lr = wm + mt * 16 + (lane >> 2) + h * 8;
                    int col = j * 8 + (lane & 3) * 2;
                    ex[lr * 66 + col]     = acc[mt][j][h * 2];
                    ex[lr * 66 + col + 1] = acc[mt][j][h * 2 + 1];
                }
    }
    __syncthreads();
    if (wid < 4) {
#pragma unroll
        for (int mt = 0; mt < 2; mt++)
#pragma unroll
            for (int j = 0; j < 8; j++)
#pragma unroll
                for (int h = 0; h < 2; h++) {
                    int lr = wm + mt * 16 + (lane >> 2) + h * 8;
                    if (row0 + lr < count) {
                        int col = j * 8 + (lane & 3) * 2;
                        float wt = swt[lr];
                        float u1a = acc[mt][j][h * 2],     u3a = ex[lr * 66 + col];
                        float u1b = acc[mt][j][h * 2 + 1], u3b = ex[lr * 66 + col + 1];
                        float ha = (u1a / (1.f + expf(-u1a))) * u3a * wt;
                        float hb = (u1b / (1.f + expf(-u1b))) * u3b * wt;
                        __half2 H = __floats2half2_rn(ha, hb);
                        size_t o = (size_t)(hbase + row0 + lr) * INTER + n0 + col;
                        *(__half2*)(g_hh + o) = H;
                    }
                }
    }
}

// ---------------- down GEMM: g_d = H_hi W2^T --------------------------------
// grid: (NBD=16, 32, NE+1); e==NE => shared expert
__global__ void __launch_bounds__(256, 2) gemm_down(int T) {
    int e = blockIdx.z;
    bool se = (e == NE);
    int count = se ? T : g_count[e];
    int row0 = blockIdx.y * 128;
    if (row0 >= count) return;
    int hbase = se ? 2 * T : g_offset[e];
    const char* pan = (const char*)g_wdn + ((size_t)e * NBD + blockIdx.x) * KCD * 8192;
    int n0 = blockIdx.x * 128;

    extern __shared__ __align__(128) char smem[];
    __shared__ __align__(8) uint64_t bars[NST];
    int tid = threadIdx.x, wid = tid >> 5, lane = tid & 31;
    uint32_t bar0 = smem_u32(bars);
    if (tid == 0) {
#pragma unroll
        for (int s = 0; s < NST; s++) mbar_init(bar0 + s * 8, 1);
    }
    __syncthreads();

    uint32_t sb = smem_u32(smem);
    uint32_t soff[2], aoff[2];
#pragma unroll
    for (int j = 0; j < 2; j++) {
        int chunk = tid + j * 256;
        int r = chunk >> 2, c4 = chunk & 3;
        soff[j] = toff((uint32_t)r, (uint32_t)c4);
        int rr = row0 + r;
        int hr = hbase + ((rr < count) ? rr : count - 1);
        aoff[j] = (uint32_t)hr * INTER + c4 * 8;
    }

    const int NIT = KCD;  // 44
    auto issueA = [&](int itn) {
        if (itn < NIT) {
            uint32_t db = sb + (uint32_t)(itn & (NST - 1)) * STAGE;
            int kk = itn * KC;
#pragma unroll
            for (int j = 0; j < 2; j++) cpa16(db + soff[j], g_hh + aoff[j] + kk);
        }
        cpcommit();
    };
    auto issueB = [&](int itn) {
        if (tid == 0 && itn < NIT) {
            uint32_t bb = bar0 + (uint32_t)(itn & (NST - 1)) * 8;
            mbar_expect_tx(bb, 8192);
            bulk_g2s(sb + (uint32_t)(itn & (NST - 1)) * STAGE + 8192,
                     pan + (size_t)itn * 8192, 8192, bb);
        }
    };
    issueB(0); issueB(1); issueB(2);
    issueA(0); issueA(1); issueA(2);

    int arow = lane & 15, asel = lane >> 4;
    int brow = (lane & 7) + ((lane & 16) >> 1), bsel = (lane >> 3) & 1;
    int wm = (wid & 3) * 32, wn = (wid >> 2) * 64;

    float acc[2][8][4] = {};
    for (int it = 0; it < NIT; it++) {
        cpwait<2>();
        mbar_wait(bar0 + (uint32_t)(it & (NST - 1)) * 8, (it >> 2) & 1);
        __syncthreads();
        issueB(it + 3);
        issueA(it + 3);
        compute_iter1(acc, sb + (uint32_t)(it & (NST - 1)) * STAGE,
                      wm, wn, arow, asel, brow, bsel);
    }

#pragma unroll
    for (int mt = 0; mt < 2; mt++)
#pragma unroll
        for (int j = 0; j < 8; j++)
#pragma unroll
            for (int h = 0; h < 2; h++) {
                int lr = wm + mt * 16 + (lane >> 2) + h * 8;
                if (row0 + lr < count) {
                    int col = n0 + wn + j * 8 + (lane & 3) * 2;
                    size_t ob = (size_t)(hbase + row0 + lr) * DIM + col;
                    *(float2*)(g_d + ob) =
                        make_float2(acc[mt][j][h * 2], acc[mt][j][h * 2 + 1]);
                }
            }
}

// ---------------- combine: out[t] = shared + routed1 + routed2 ------------
__global__ void combine_kernel(float* __restrict__ out, int T) {
    int t = blockIdx.x;
    int r1 = g_offset[g_exp[2 * t]]     + g_pos[2 * t];
    int r2 = g_offset[g_exp[2 * t + 1]] + g_pos[2 * t + 1];
    const float4* ps = (const float4*)(g_d + (size_t)(2 * T + t) * DIM);
    const float4* p1 = (const float4*)(g_d + (size_t)r1 * DIM);
    const float4* p2 = (const float4*)(g_d + (size_t)r2 * DIM);
    float4* po = (float4*)(out + (size_t)t * DIM);
#pragma unroll
    for (int q = 0; q < 2; q++) {
        int c = threadIdx.x + q * 256;  // 512 float4 per row
        float4 a = ps[c], b = p1[c], d = p2[c];
        po[c] = make_float4(a.x + b.x + d.x, a.y + b.y + d.y,
                            a.z + b.z + d.z, a.w + b.w + d.w);
    }
}

// ---------------- entry point ----------------------------------------------
extern "C" void kernel_launch(void* const* d_in, const int* in_sizes, int n_in,
                              void* d_out, int out_size) {
    const float* x   = (const float*)d_in[0];
    const float* gw  = (const float*)d_in[1];
    const float* w1  = (const float*)d_in[2];
    const float* w3  = (const float*)d_in[3];
    const float* w2  = (const float*)d_in[4];
    const float* sw1 = (const float*)d_in[5];
    const float* sw3 = (const float*)d_in[6];
    const float* sw2 = (const float*)d_in[7];
    float* out = (float*)d_out;

    int T = in_sizes[0] / DIM;  // 4096

    const int SM = NST * STAGE;  // 64 KB
    cudaFuncSetAttribute(gemm_up,   cudaFuncAttributeMaxDynamicSharedMemorySize, SM);
    cudaFuncSetAttribute(gemm_down, cudaFuncAttributeMaxDynamicSharedMemorySize, SM);

    // lazily created once (non-captured correctness call); reused in capture
    static cudaStream_t sA = 0, sB = 0;
    static cudaEvent_t  evF = 0, evW2 = 0, evG = 0;
    if (!sA) {
        cudaStreamCreateWithFlags(&sA, cudaStreamNonBlocking);
        cudaStreamCreateWithFlags(&sB, cudaStreamNonBlocking);
        cudaEventCreateWithFlags(&evF,  cudaEventDisableTiming);
        cudaEventCreateWithFlags(&evW2, cudaEventDisableTiming);
        cudaEventCreateWithFlags(&evG,  cudaEventDisableTiming);
    }

    __half* xh;
    cudaGetSymbolAddress((void**)&xh, g_xh);
    int nx8 = T * DIM / 8;

    // fork point
    cudaEventRecord(evF, 0);

    // sA: down weight pack (needed only by gemm_down)
    cudaStreamWaitEvent(sA, evF, 0);
    pack_dn<<<dim3(NBD, KCD, NE + 1), 256, 0, sA>>>(w2, sw2);
    cudaEventRecord(evW2, sA);

    // sB: gating
    cudaStreamWaitEvent(sB, evF, 0);
    reset_kernel<<<1, 32, 0, sB>>>();
    gate_kernel<<<(T + 7) / 8, 256, 0, sB>>>(x, gw, T);
    offset_kernel<<<1, 1, 0, sB>>>();
    cudaEventRecord(evG, sB);

    // main: x convert + up weight pack
    cvt_x<<<(nx8 + 1023) / 1024, 256>>>((const float4*)x, (uint4*)xh, nx8);
    pack_up<<<dim3(NBU, KCU, NE + 1), 256>>>(w1, w3, sw1, sw3);

    cudaStreamWaitEvent(0, evG, 0);
    dim3 gup(NBU, (T + 127) / 128, NE + 1);
    gemm_up<<<gup, 256, SM>>>(T);

    cudaStreamWaitEvent(0, evW2, 0);
    dim3 gdn(NBD, (T + 127) / 128, NE + 1);
    gemm_down<<<gdn, 256, SM>>>(T);

    combine_kernel<<<T, 256>>>(out, T);
}